// round 12
// baseline (speedup 1.0000x reference)
#include <cuda_runtime.h>
#include <math.h>

#define Bb   4
#define Nn   512
#define Dd   48
#define H1   96
#define BN   (Bb * Nn)
#define TPB  128
#define NW   (TPB / 32)
#define JT   TPB
#define FULLM 0xFFFFFFFFu

typedef unsigned long long u64;

__device__ __align__(16) float g_A[BN * H1];        // A[bn][k] = x@W1_top + b1
__device__ __align__(16) float g_C[BN * H1];        // C[bn][k] = x@W1_bot
__device__ __align__(16) float g_G[Bb * Nn * Nn * H1]; // G[b,i,j,k] = gelu(A+C), triangle

__device__ __forceinline__ float gelu_exact(float v) {
    return 0.5f * v * (1.0f + erff(v * 0.70710678118654752f));
}
__device__ __forceinline__ u64 pk(float lo, float hi) {
    u64 r; asm("mov.b64 %0, {%1,%2};" : "=l"(r) : "f"(lo), "f"(hi)); return r;
}
__device__ __forceinline__ u64 pk1(float v) { return pk(v, v); }
__device__ __forceinline__ void upk(u64 v, float& lo, float& hi) {
    asm("mov.b64 {%0,%1}, %2;" : "=f"(lo), "=f"(hi) : "l"(v));
}
__device__ __forceinline__ u64 ffma2(u64 a, u64 b, u64 c) {
    u64 d; asm("fma.rn.f32x2 %0, %1, %2, %3;" : "=l"(d) : "l"(a), "l"(b), "l"(c)); return d;
}
__device__ __forceinline__ u64 fmul2(u64 a, u64 b) {
    u64 d; asm("mul.rn.f32x2 %0, %1, %2;" : "=l"(d) : "l"(a), "l"(b)); return d;
}
__device__ __forceinline__ u64 fadd2(u64 a, u64 b) {
    u64 d; asm("add.rn.f32x2 %0, %1, %2;" : "=l"(d) : "l"(a), "l"(b)); return d;
}

// ---------------------------------------------------------------------------
// Kernel 1: per-token halves of the first linear layer (tiny).
// ---------------------------------------------------------------------------
__global__ void prep_kernel(const float* __restrict__ x,
                            const float* __restrict__ W1,
                            const float* __restrict__ b1) {
    int bn = blockIdx.x;
    int k  = threadIdx.x;            // 0..95
    __shared__ float sx[Dd];
    if (k < Dd) sx[k] = x[bn * Dd + k];
    __syncthreads();
    float a = b1[k], c = 0.0f;
#pragma unroll
    for (int d = 0; d < Dd; d++) {
        float xv = sx[d];
        a += xv * W1[d * H1 + k];
        c += xv * W1[(Dd + d) * H1 + k];
    }
    g_A[bn * H1 + k] = a;
    g_C[bn * H1 + k] = c;
}

// ---------------------------------------------------------------------------
// Kernel 1b: G[b,i,j,k] = gelu(A[b,i,k] + C[b,j,k]) for j <= i.
// Pure streaming: no dependency chains, gelu at near-full issue.
// One CTA per (b,i) [bit-reversed i for wave balance], 256 threads.
// ---------------------------------------------------------------------------
__global__ __launch_bounds__(256)
void gelu_kernel() {
    const int idx = blockIdx.x;
    const int b   = idx & 3;
    const int i   = (int)(__brev((unsigned)(idx >> 2)) >> 23);   // 9-bit reverse

    __shared__ __align__(16) float sA[H1];
    if (threadIdx.x < H1) sA[threadIdx.x] = g_A[(b * Nn + i) * H1 + threadIdx.x];
    __syncthreads();

    const float4* __restrict__ C4 = (const float4*)&g_C[b * Nn * H1];
    float4* __restrict__ G4 = (float4*)&g_G[(size_t)(b * Nn + i) * Nn * H1];
    const float4* sA4 = (const float4*)sA;

    const int nq = (i + 1) * (H1 / 4);           // quads to produce
    for (int q = threadIdx.x; q < nq; q += 256) {
        int j  = q / (H1 / 4);
        int kq = q - j * (H1 / 4);
        float4 c = C4[j * (H1 / 4) + kq];
        float4 a = sA4[kq];
        float4 g;
        g.x = gelu_exact(a.x + c.x);
        g.y = gelu_exact(a.y + c.y);
        g.z = gelu_exact(a.z + c.z);
        g.w = gelu_exact(a.w + c.w);
        G4[q] = g;
    }
}

// ---------------------------------------------------------------------------
// Kernel 2: one CTA per (b,i) [bit-reversed]. Lane groups of 4: lane sub s
// owns d-quarter [12s,12s+12); each group carries FOUR j columns. Layer-2
// gelu values come straight from precomputed G via LDG.128 — no gelu, no
// shfl, no serial chain in the k-loop. Warp-granular tile skip.
// ---------------------------------------------------------------------------
__global__ __launch_bounds__(TPB, 3)
void pair_kernel(const float* __restrict__ W2g, const float* __restrict__ b2g,
                 const float* __restrict__ W3g, const float* __restrict__ b3g,
                 float* __restrict__ out) {
    __shared__ __align__(16) float sW2[H1 * Dd];
    __shared__ __align__(16) float sW3[Dd * Dd];
    __shared__ __align__(16) float sB2[Dd];
    __shared__ __align__(16) float sB3[Dd];
    __shared__ float sRed[16];
    __shared__ float sAcc[NW * Dd];

    const int idx = blockIdx.x;
    const int b   = idx & 3;
    const int i   = (int)(__brev((unsigned)(idx >> 2)) >> 23);
    const int bi  = b * Nn + i;

    const int tid = threadIdx.x, lane = tid & 31, wid = tid >> 5;
    const int sub = tid & 3;
    const int dbase = sub * 12;
    const int gsrc = lane & ~3;

    for (int t = tid; t < H1 * Dd; t += TPB) sW2[t] = W2g[t];
    for (int t = tid; t < Dd * Dd; t += TPB) sW3[t] = W3g[t];
    if (tid < Dd) { sB2[tid] = b2g[tid]; sB3[tid] = b3g[tid]; }
    __syncthreads();

    const float4* __restrict__ Grow = (const float4*)&g_G[(size_t)bi * Nn * H1];

    float mloc = -1e30f, sloc = 0.0f;
    u64 acc[6];
#pragma unroll
    for (int u = 0; u < 6; u++) acc[u] = pk(0.0f, 0.0f);

    for (int jb = 0; jb <= i; jb += JT) {
        if (jb + (wid << 5) > i) continue;        // warp-uniform skip

        const int jg = jb + (tid & ~3);           // group's first j (uniform in group)

        // ================= layer 2: h2[jj] = G_j @ W2 + b2 =================
        u64 h2[4][6];
#pragma unroll
        for (int u = 0; u < 6; u++) {
            u64 bb = *(const u64*)(sB2 + dbase + 2 * u);
            h2[0][u] = bb; h2[1][u] = bb; h2[2][u] = bb; h2[3][u] = bb;
        }

        // four G row pointers (rows jg..jg+3; rows > i read benign data)
        const float4* __restrict__ r0p = Grow + (size_t)(jg + 0) * (H1 / 4);
        const float4* __restrict__ r1p = Grow + (size_t)(jg + 1) * (H1 / 4);
        const float4* __restrict__ r2p = Grow + (size_t)(jg + 2) * (H1 / 4);
        const float4* __restrict__ r3p = Grow + (size_t)(jg + 3) * (H1 / 4);

        float4 mf0 = r0p[0], mf1 = r1p[0], mf2 = r2p[0], mf3 = r3p[0];
#pragma unroll 1
        for (int kk = 0; kk < H1 / 4; kk++) {
            float4 nf0, nf1, nf2, nf3;
            if (kk + 1 < H1 / 4) {               // next body's loads first (MLP=4)
                nf0 = r0p[kk + 1]; nf1 = r1p[kk + 1];
                nf2 = r2p[kk + 1]; nf3 = r3p[kk + 1];
            }
            const float gv[4][4] = {
                {mf0.x, mf0.y, mf0.z, mf0.w},
                {mf1.x, mf1.y, mf1.z, mf1.w},
                {mf2.x, mf2.y, mf2.z, mf2.w},
                {mf3.x, mf3.y, mf3.z, mf3.w}};
#pragma unroll
            for (int t = 0; t < 4; t++) {
                u64 m0 = pk1(gv[0][t]);
                u64 m1 = pk1(gv[1][t]);
                u64 m2 = pk1(gv[2][t]);
                u64 m3 = pk1(gv[3][t]);
                const float* wr = &sW2[(4 * kk + t) * Dd + dbase];
                ulonglong2 w0 = *(const ulonglong2*)(wr);
                ulonglong2 w1 = *(const ulonglong2*)(wr + 4);
                ulonglong2 w2 = *(const ulonglong2*)(wr + 8);
                h2[0][0] = ffma2(m0, w0.x, h2[0][0]);
                h2[0][1] = ffma2(m0, w0.y, h2[0][1]);
                h2[0][2] = ffma2(m0, w1.x, h2[0][2]);
                h2[0][3] = ffma2(m0, w1.y, h2[0][3]);
                h2[0][4] = ffma2(m0, w2.x, h2[0][4]);
                h2[0][5] = ffma2(m0, w2.y, h2[0][5]);
                h2[1][0] = ffma2(m1, w0.x, h2[1][0]);
                h2[1][1] = ffma2(m1, w0.y, h2[1][1]);
                h2[1][2] = ffma2(m1, w1.x, h2[1][2]);
                h2[1][3] = ffma2(m1, w1.y, h2[1][3]);
                h2[1][4] = ffma2(m1, w2.x, h2[1][4]);
                h2[1][5] = ffma2(m1, w2.y, h2[1][5]);
                h2[2][0] = ffma2(m2, w0.x, h2[2][0]);
                h2[2][1] = ffma2(m2, w0.y, h2[2][1]);
                h2[2][2] = ffma2(m2, w1.x, h2[2][2]);
                h2[2][3] = ffma2(m2, w1.y, h2[2][3]);
                h2[2][4] = ffma2(m2, w2.x, h2[2][4]);
                h2[2][5] = ffma2(m2, w2.y, h2[2][5]);
                h2[3][0] = ffma2(m3, w0.x, h2[3][0]);
                h2[3][1] = ffma2(m3, w0.y, h2[3][1]);
                h2[3][2] = ffma2(m3, w1.x, h2[3][2]);
                h2[3][3] = ffma2(m3, w1.y, h2[3][3]);
                h2[3][4] = ffma2(m3, w2.x, h2[3][4]);
                h2[3][5] = ffma2(m3, w2.y, h2[3][5]);
            }
            mf0 = nf0; mf1 = nf1; mf2 = nf2; mf3 = nf3;
        }

        // ======= gelu of h2 in place (own d-quarter, all 4 j's) ============
#pragma unroll
        for (int jj = 0; jj < 4; jj++)
#pragma unroll
            for (int u = 0; u < 6; u++) {
                float lo, hi; upk(h2[jj][u], lo, hi);
                h2[jj][u] = pk(gelu_exact(lo), gelu_exact(hi));
            }

        // ================= layer 3: o[jj] = gelu(h2) @ W3 + b3 =============
        u64 o[4][6];
#pragma unroll
        for (int u = 0; u < 6; u++) {
            u64 bb = *(const u64*)(sB3 + dbase + 2 * u);
            o[0][u] = bb; o[1][u] = bb; o[2][u] = bb; o[3][u] = bb;
        }
#pragma unroll 1
        for (int srcs = 0; srcs < 4; srcs++) {
            int src = gsrc + srcs;
            const float* rbase = &sW3[srcs * 12 * Dd + dbase];
#pragma unroll
            for (int u = 0; u < 6; u++) {
                const float* r0 = rbase + (2 * u) * Dd;
                const float* r1 = rbase + (2 * u + 1) * Dd;
                ulonglong2 a0 = *(const ulonglong2*)(r0);
                ulonglong2 a1 = *(const ulonglong2*)(r0 + 4);
                ulonglong2 a2 = *(const ulonglong2*)(r0 + 8);
                ulonglong2 c0 = *(const ulonglong2*)(r1);
                ulonglong2 c1 = *(const ulonglong2*)(r1 + 4);
                ulonglong2 c2 = *(const ulonglong2*)(r1 + 8);
#pragma unroll
                for (int jj = 0; jj < 4; jj++) {
                    u64 gpair = __shfl_sync(FULLM, h2[jj][u], src);
                    float glo, ghi; upk(gpair, glo, ghi);
                    u64 plo = pk1(glo), phi = pk1(ghi);
                    o[jj][0] = ffma2(plo, a0.x, ffma2(phi, c0.x, o[jj][0]));
                    o[jj][1] = ffma2(plo, a0.y, ffma2(phi, c0.y, o[jj][1]));
                    o[jj][2] = ffma2(plo, a1.x, ffma2(phi, c1.x, o[jj][2]));
                    o[jj][3] = ffma2(plo, a1.y, ffma2(phi, c1.y, o[jj][3]));
                    o[jj][4] = ffma2(plo, a2.x, ffma2(phi, c2.x, o[jj][4]));
                    o[jj][5] = ffma2(plo, a2.y, ffma2(phi, c2.y, o[jj][5]));
                }
            }
        }

        // ============== norms + online softmax (group-consistent) ==========
#pragma unroll
        for (int jj = 0; jj < 4; jj++) {
            float n = 0.0f;
#pragma unroll
            for (int u = 0; u < 6; u++) {
                float x0, x1; upk(fmul2(o[jj][u], o[jj][u]), x0, x1);
                n += x0 + x1;
            }
            n += __shfl_xor_sync(FULLM, n, 1);
            n += __shfl_xor_sync(FULLM, n, 2);
            if (jg + jj <= i) {
                float w  = sqrtf(n);
                float mn = fmaxf(mloc, w);
                float rr = __expf(mloc - mn), ee = __expf(w - mn);
                sloc = sloc * rr + ((jj == sub) ? ee : 0.0f);
                u64 rp = pk1(rr), ep = pk1(ee);
#pragma unroll
                for (int u = 0; u < 6; u++)
                    acc[u] = ffma2(acc[u], rp, fmul2(o[jj][u], ep));
                mloc = mn;
            }
        }
    }

    // ---- block max ----
    float M = mloc;
#pragma unroll
    for (int off = 16; off; off >>= 1) M = fmaxf(M, __shfl_xor_sync(FULLM, M, off));
    if (lane == 0) sRed[wid] = M;
    __syncthreads();
    if (tid == 0) {
        float m = sRed[0];
#pragma unroll
        for (int w = 1; w < NW; w++) m = fmaxf(m, sRed[w]);
        sRed[8] = m;
    }
    __syncthreads();
    M = sRed[8];

    // ---- rescale + denominator + accumulator reduce ----
    float sc = __expf(mloc - M);
    float ss = sloc * sc;
#pragma unroll
    for (int off = 16; off; off >>= 1) ss += __shfl_xor_sync(FULLM, ss, off);
    if (lane == 0) sRed[wid] = ss;

    u64 scp = pk1(sc);
#pragma unroll
    for (int u = 0; u < 6; u++) {
        u64 v = fmul2(acc[u], scp);
        v = fadd2(v, __shfl_xor_sync(FULLM, v, 4));
        v = fadd2(v, __shfl_xor_sync(FULLM, v, 8));
        v = fadd2(v, __shfl_xor_sync(FULLM, v, 16));
        acc[u] = v;
    }
    if (lane < 4) {
#pragma unroll
        for (int u = 0; u < 6; u++) {
            float x0, x1; upk(acc[u], x0, x1);
            sAcc[wid * Dd + dbase + 2 * u]     = x0;
            sAcc[wid * Dd + dbase + 2 * u + 1] = x1;
        }
    }
    __syncthreads();
    if (tid == 0) {
        float s = sRed[0];
#pragma unroll
        for (int w = 1; w < NW; w++) s += sRed[w];
        sRed[9] = 1.0f / s;
    }
    __syncthreads();
    if (tid < Dd) {
        float a = 0.0f;
#pragma unroll
        for (int w = 0; w < NW; w++) a += sAcc[w * Dd + tid];
        out[bi * Dd + tid] = a * sRed[9];
    }
}

// ---------------------------------------------------------------------------
extern "C" void kernel_launch(void* const* d_in, const int* in_sizes, int n_in,
                              void* d_out, int out_size) {
    const float* x  = (const float*)d_in[0];
    const float* W1 = (const float*)d_in[1];
    const float* b1 = (const float*)d_in[2];
    const float* W2 = (const float*)d_in[3];
    const float* b2 = (const float*)d_in[4];
    const float* W3 = (const float*)d_in[5];
    const float* b3 = (const float*)d_in[6];
    float* out = (float*)d_out;

    prep_kernel<<<BN, H1>>>(x, W1, b1);
    gelu_kernel<<<BN, 256>>>();
    pair_kernel<<<BN, TPB>>>(W2, b2, W3, b3, out);
    (void)in_sizes; (void)n_in; (void)out_size;
}

// round 13
// speedup vs baseline: 1.2430x; 1.2430x over previous
#include <cuda_runtime.h>
#include <math.h>

#define Bb   4
#define Nn   512
#define Dd   48
#define H1   96
#define BN   (Bb * Nn)
#define TPB  128
#define NW   (TPB / 32)
#define JT   TPB            // j's per tile (one j per thread)

typedef unsigned long long u64;

__device__ __align__(16) float g_A[BN * H1];   // A[bn][k] = x@W1_top + b1
__device__ __align__(16) float g_C[BN * H1];   // C[bn][k] = x@W1_bot

// Fast gelu: Abramowitz-Stegun 7.1.26 erf (|err| <= 1.5e-7).
// Moves the transcendental off the FMA pipe: 2 MUFU (RCP, EX2) + ~6 FMA,
// vs ~20 FMA-pipe ops for libdevice erff.
__device__ __forceinline__ float gelu_exact(float v) {
    float x  = v * 0.70710678118654752f;
    float ax = fabsf(x);
    float t  = __fdividef(1.0f, fmaf(0.3275911f, ax, 1.0f));   // MUFU RCP
    float p  = fmaf(1.061405429f, t, -1.453152027f);
    p = fmaf(p, t, 1.421413741f);
    p = fmaf(p, t, -0.284496736f);
    p = fmaf(p, t, 0.254829592f);
    float e  = __expf(-x * x);                                  // MUFU EX2
    float y  = 1.0f - p * t * e;
    float er = copysignf(y, x);
    return 0.5f * v * (1.0f + er);
}
__device__ __forceinline__ u64 pk(float lo, float hi) {
    u64 r; asm("mov.b64 %0, {%1,%2};" : "=l"(r) : "f"(lo), "f"(hi)); return r;
}
__device__ __forceinline__ u64 pk1(float v) { return pk(v, v); }
__device__ __forceinline__ void upk(u64 v, float& lo, float& hi) {
    asm("mov.b64 {%0,%1}, %2;" : "=f"(lo), "=f"(hi) : "l"(v));
}
__device__ __forceinline__ u64 ffma2(u64 a, u64 b, u64 c) {
    u64 d; asm("fma.rn.f32x2 %0, %1, %2, %3;" : "=l"(d) : "l"(a), "l"(b), "l"(c)); return d;
}
__device__ __forceinline__ u64 fmul2(u64 a, u64 b) {
    u64 d; asm("mul.rn.f32x2 %0, %1, %2;" : "=l"(d) : "l"(a), "l"(b)); return d;
}
__device__ __forceinline__ u64 fadd2(u64 a, u64 b) {
    u64 d; asm("add.rn.f32x2 %0, %1, %2;" : "=l"(d) : "l"(a), "l"(b)); return d;
}

// ---------------------------------------------------------------------------
// Kernel 1: per-token halves of the first linear layer (tiny).
// ---------------------------------------------------------------------------
__global__ void prep_kernel(const float* __restrict__ x,
                            const float* __restrict__ W1,
                            const float* __restrict__ b1) {
    int bn = blockIdx.x;
    int k  = threadIdx.x;            // 0..95
    __shared__ float sx[Dd];
    if (k < Dd) sx[k] = x[bn * Dd + k];
    __syncthreads();
    float a = b1[k], c = 0.0f;
#pragma unroll
    for (int d = 0; d < Dd; d++) {
        float xv = sx[d];
        a += xv * W1[d * H1 + k];
        c += xv * W1[(Dd + d) * H1 + k];
    }
    g_A[bn * H1 + k] = a;
    g_C[bn * H1 + k] = c;
}

// ---------------------------------------------------------------------------
// Kernel 2: one CTA per (b,i) [i bit-reversed across blocks for wave balance].
// Lane groups of 4: lane sub s owns d-quarter [12s, 12s+12). Each group
// carries FOUR j columns; gelu streams shared via shfl.
// WARP-granular mask skip (warp-uniform condition releases issue slots).
// (Structure identical to the 297.5us R10 kernel; only gelu impl changed.)
// ---------------------------------------------------------------------------
__global__ __launch_bounds__(TPB, 3)
void pair_kernel(const float* __restrict__ W2g, const float* __restrict__ b2g,
                 const float* __restrict__ W3g, const float* __restrict__ b3g,
                 float* __restrict__ out) {
    __shared__ __align__(16) float sW2[H1 * Dd];
    __shared__ __align__(16) float sW3[Dd * Dd];
    __shared__ __align__(16) float sA[H1];
    __shared__ __align__(16) float sB2[Dd];
    __shared__ __align__(16) float sB3[Dd];
    __shared__ float sRed[16];
    __shared__ float sAcc[NW * Dd];

    // bit-reversed i assignment: every wave gets a uniform mix of small/large i
    const int idx = blockIdx.x;
    const int b   = idx & 3;
    const int i   = (int)(__brev((unsigned)(idx >> 2)) >> 23);   // 9-bit reverse
    const int bi  = b * Nn + i;

    const int tid = threadIdx.x, lane = tid & 31, wid = tid >> 5;
    const int sub = tid & 3;
    const int dbase = sub * 12;
    const int gsrc = lane & ~3;            // first lane of my group

    for (int t = tid; t < H1 * Dd; t += TPB) sW2[t] = W2g[t];
    for (int t = tid; t < Dd * Dd; t += TPB) sW3[t] = W3g[t];
    if (tid < H1) sA[tid] = g_A[bi * H1 + tid];
    if (tid < Dd) { sB2[tid] = b2g[tid]; sB3[tid] = b3g[tid]; }
    __syncthreads();

    float mloc = -1e30f, sloc = 0.0f;
    u64 acc[6];
#pragma unroll
    for (int u = 0; u < 6; u++) acc[u] = pk(0.0f, 0.0f);

    for (int jb = 0; jb <= i; jb += JT) {
        // warp-uniform skip: this warp's smallest j is jb + 32*wid
        if (jb + (wid << 5) > i) continue;

        const int jg   = jb + (tid & ~3);        // group's first j
        const int jown = jb + tid;               // always < Nn

        // ================= layer 2: h2[jj] = gelu(A_i + C_j) @ W2 + b2 =====
        u64 h2[4][6];
#pragma unroll
        for (int u = 0; u < 6; u++) {
            u64 bb = *(const u64*)(sB2 + dbase + 2 * u);
            h2[0][u] = bb; h2[1][u] = bb; h2[2][u] = bb; h2[3][u] = bb;
        }

        const float4* __restrict__ c4 = (const float4*)&g_C[(b * Nn + jown) * H1];
        float4 cv = c4[0];
#pragma unroll 1
        for (int kk = 0; kk < H1 / 4; kk++) {
            float4 cvn = (kk + 1 < H1 / 4) ? c4[kk + 1] : cv;
            float4 av = *(const float4*)(sA + 4 * kk);
            float g0 = gelu_exact(av.x + cv.x);
            float g1 = gelu_exact(av.y + cv.y);
            float g2 = gelu_exact(av.z + cv.z);
            float g3 = gelu_exact(av.w + cv.w);

            u64 m[4][4];
#pragma unroll
            for (int s = 0; s < 4; s++) {
                int src = gsrc + s;
                m[s][0] = pk1(__shfl_sync(0xFFFFFFFFu, g0, src));
                m[s][1] = pk1(__shfl_sync(0xFFFFFFFFu, g1, src));
                m[s][2] = pk1(__shfl_sync(0xFFFFFFFFu, g2, src));
                m[s][3] = pk1(__shfl_sync(0xFFFFFFFFu, g3, src));
            }
#pragma unroll
            for (int t = 0; t < 4; t++) {
                const float* wr = &sW2[(4 * kk + t) * Dd + dbase];
                ulonglong2 w0 = *(const ulonglong2*)(wr);
                ulonglong2 w1 = *(const ulonglong2*)(wr + 4);
                ulonglong2 w2 = *(const ulonglong2*)(wr + 8);
#pragma unroll
                for (int s = 0; s < 4; s++) {
                    h2[s][0] = ffma2(m[s][t], w0.x, h2[s][0]);
                    h2[s][1] = ffma2(m[s][t], w0.y, h2[s][1]);
                    h2[s][2] = ffma2(m[s][t], w1.x, h2[s][2]);
                    h2[s][3] = ffma2(m[s][t], w1.y, h2[s][3]);
                    h2[s][4] = ffma2(m[s][t], w2.x, h2[s][4]);
                    h2[s][5] = ffma2(m[s][t], w2.y, h2[s][5]);
                }
            }
            cv = cvn;
        }

        // ======= gelu of h2 in place (own d-quarter, all 4 j's) ============
#pragma unroll
        for (int jj = 0; jj < 4; jj++)
#pragma unroll
            for (int u = 0; u < 6; u++) {
                float lo, hi; upk(h2[jj][u], lo, hi);
                h2[jj][u] = pk(gelu_exact(lo), gelu_exact(hi));
            }

        // ================= layer 3: o[jj] = gelu(h2) @ W3 + b3 =============
        u64 o[4][6];
#pragma unroll
        for (int u = 0; u < 6; u++) {
            u64 bb = *(const u64*)(sB3 + dbase + 2 * u);
            o[0][u] = bb; o[1][u] = bb; o[2][u] = bb; o[3][u] = bb;
        }
#pragma unroll 1
        for (int srcs = 0; srcs < 4; srcs++) {
            int src = gsrc + srcs;
            const float* rbase = &sW3[srcs * 12 * Dd + dbase];
#pragma unroll
            for (int u = 0; u < 6; u++) {
                const float* r0 = rbase + (2 * u) * Dd;
                const float* r1 = rbase + (2 * u + 1) * Dd;
                ulonglong2 a0 = *(const ulonglong2*)(r0);
                ulonglong2 a1 = *(const ulonglong2*)(r0 + 4);
                ulonglong2 a2 = *(const ulonglong2*)(r0 + 8);
                ulonglong2 c0 = *(const ulonglong2*)(r1);
                ulonglong2 c1 = *(const ulonglong2*)(r1 + 4);
                ulonglong2 c2 = *(const ulonglong2*)(r1 + 8);
#pragma unroll
                for (int jj = 0; jj < 4; jj++) {
                    u64 gpair = __shfl_sync(0xFFFFFFFFu, h2[jj][u], src);
                    float glo, ghi; upk(gpair, glo, ghi);
                    u64 plo = pk1(glo), phi = pk1(ghi);
                    o[jj][0] = ffma2(plo, a0.x, ffma2(phi, c0.x, o[jj][0]));
                    o[jj][1] = ffma2(plo, a0.y, ffma2(phi, c0.y, o[jj][1]));
                    o[jj][2] = ffma2(plo, a1.x, ffma2(phi, c1.x, o[jj][2]));
                    o[jj][3] = ffma2(plo, a1.y, ffma2(phi, c1.y, o[jj][3]));
                    o[jj][4] = ffma2(plo, a2.x, ffma2(phi, c2.x, o[jj][4]));
                    o[jj][5] = ffma2(plo, a2.y, ffma2(phi, c2.y, o[jj][5]));
                }
            }
        }

        // ============== norms + online softmax (group-consistent) ==========
#pragma unroll
        for (int jj = 0; jj < 4; jj++) {
            float n = 0.0f;
#pragma unroll
            for (int u = 0; u < 6; u++) {
                float x0, x1; upk(fmul2(o[jj][u], o[jj][u]), x0, x1);
                n += x0 + x1;
            }
            n += __shfl_xor_sync(0xFFFFFFFFu, n, 1);
            n += __shfl_xor_sync(0xFFFFFFFFu, n, 2);
            if (jg + jj <= i) {
                float w  = sqrtf(n);
                float mn = fmaxf(mloc, w);
                float rr = __expf(mloc - mn), ee = __expf(w - mn);
                sloc = sloc * rr + ((jj == sub) ? ee : 0.0f);
                u64 rp = pk1(rr), ep = pk1(ee);
#pragma unroll
                for (int u = 0; u < 6; u++)
                    acc[u] = ffma2(acc[u], rp, fmul2(o[jj][u], ep));
                mloc = mn;
            }
        }
    }

    // ---- block max ----
    float M = mloc;
#pragma unroll
    for (int off = 16; off; off >>= 1) M = fmaxf(M, __shfl_xor_sync(0xFFFFFFFFu, M, off));
    if (lane == 0) sRed[wid] = M;
    __syncthreads();
    if (tid == 0) {
        float m = sRed[0];
#pragma unroll
        for (int w = 1; w < NW; w++) m = fmaxf(m, sRed[w]);
        sRed[8] = m;
    }
    __syncthreads();
    M = sRed[8];

    // ---- rescale + denominator + accumulator reduce ----
    float sc = __expf(mloc - M);
    float ss = sloc * sc;
#pragma unroll
    for (int off = 16; off; off >>= 1) ss += __shfl_xor_sync(0xFFFFFFFFu, ss, off);
    if (lane == 0) sRed[wid] = ss;

    u64 scp = pk1(sc);
#pragma unroll
    for (int u = 0; u < 6; u++) {
        u64 v = fmul2(acc[u], scp);
        v = fadd2(v, __shfl_xor_sync(0xFFFFFFFFu, v, 4));
        v = fadd2(v, __shfl_xor_sync(0xFFFFFFFFu, v, 8));
        v = fadd2(v, __shfl_xor_sync(0xFFFFFFFFu, v, 16));
        acc[u] = v;                    // lanes 0..3 hold warp totals per d-quarter
    }
    if (lane < 4) {
#pragma unroll
        for (int u = 0; u < 6; u++) {
            float x0, x1; upk(acc[u], x0, x1);
            sAcc[wid * Dd + dbase + 2 * u]     = x0;
            sAcc[wid * Dd + dbase + 2 * u + 1] = x1;
        }
    }
    __syncthreads();
    if (tid == 0) {
        float s = sRed[0];
#pragma unroll
        for (int w = 1; w < NW; w++) s += sRed[w];
        sRed[9] = 1.0f / s;
    }
    __syncthreads();
    if (tid < Dd) {
        float a = 0.0f;
#pragma unroll
        for (int w = 0; w < NW; w++) a += sAcc[w * Dd + tid];
        out[bi * Dd + tid] = a * sRed[9];
    }
}

// ---------------------------------------------------------------------------
extern "C" void kernel_launch(void* const* d_in, const int* in_sizes, int n_in,
                              void* d_out, int out_size) {
    const float* x  = (const float*)d_in[0];
    const float* W1 = (const float*)d_in[1];
    const float* b1 = (const float*)d_in[2];
    const float* W2 = (const float*)d_in[3];
    const float* b2 = (const float*)d_in[4];
    const float* W3 = (const float*)d_in[5];
    const float* b3 = (const float*)d_in[6];
    float* out = (float*)d_out;

    prep_kernel<<<BN, H1>>>(x, W1, b1);
    pair_kernel<<<BN, TPB>>>(W2, b2, W3, b3, out);
    (void)in_sizes; (void)n_in; (void)out_size;
}